// round 10
// baseline (speedup 1.0000x reference)
#include <cuda_runtime.h>
#include <cuda_bf16.h>
#include <cstdint>

// ---------------------------------------------------------------------------
#define Mn  16384
#define Nn  8192
#define Kn  256
#define HWn 1024
#define Bln 16

#define OUT_ZQ  (Mn * Kn)
#define OUT_IDX (2 * Mn * Kn)

#define CERT_WINDOW 3.5f
#define NCAND 16
#define NTILE 32        // tiles per CTA (half of N)

// ---------------------------------------------------------------------------
__device__ __align__(16) int8_t g_qz[Mn * Kn];
__device__ __align__(16) int8_t g_qw[Nn * Kn];
__device__ float g_izs[Mn];
__device__ float g_iws[Nn];
__device__ float g_wnorm[Nn];
__device__ int   g_bestidx[Mn];
__device__ int   g_cand[Mn][2][NCAND];
__device__ int   g_flag[Mn];
__device__ int   g_flag_list[Mn];
__device__ int   g_flag_count;

// ---------------------------------------------------------------------------
__device__ __forceinline__ uint32_t smem_u32(const void* p) {
    uint32_t a;
    asm("{ .reg .u64 t; cvta.to.shared.u64 t, %1; cvt.u32.u64 %0, t; }"
        : "=r"(a) : "l"(p));
    return a;
}
__device__ __forceinline__ void cp_async16(uint32_t dst, const void* src) {
    asm volatile("cp.async.cg.shared.global [%0], [%1], 16;"
                 :: "r"(dst), "l"(src) : "memory");
}
#define MBAR_INIT(a, c) \
    asm volatile("mbarrier.init.shared.b64 [%0], %1;" :: "r"(a), "r"(c) : "memory")
#define MBAR_ARRIVE(a) \
    asm volatile("mbarrier.arrive.shared.b64 _, [%0];" :: "r"(a) : "memory")
#define CPASYNC_MBAR_ARRIVE(a) \
    asm volatile("cp.async.mbarrier.arrive.noinc.shared.b64 [%0];" :: "r"(a) : "memory")

__device__ __forceinline__ void mbar_wait(uint32_t addr, uint32_t parity) {
    asm volatile(
        "{\n\t"
        ".reg .pred P;\n\t"
        "WL_%=:\n\t"
        "mbarrier.try_wait.parity.acquire.cta.shared::cta.b64 P, [%0], %1, 0x989680;\n\t"
        "@P bra.uni WD_%=;\n\t"
        "bra.uni WL_%=;\n\t"
        "WD_%=:\n\t"
        "}"
        :: "r"(addr), "r"(parity) : "memory");
}

#define LDSM_X4(r0, r1, r2, r3, a) \
    asm volatile("ldmatrix.sync.aligned.m8n8.x4.shared.b16 {%0,%1,%2,%3}, [%4];" \
                 : "=r"(r0), "=r"(r1), "=r"(r2), "=r"(r3) : "r"(a))

#define IMMA16832(c, a, b) \
    asm volatile("mma.sync.aligned.m16n8k32.row.col.s32.s8.s8.s32 " \
                 "{%0,%1,%2,%3}, {%4,%5,%6,%7}, {%8,%9}, {%0,%1,%2,%3};" \
                 : "+r"((c)[0]), "+r"((c)[1]), "+r"((c)[2]), "+r"((c)[3]) \
                 : "r"((a)[0]), "r"((a)[1]), "r"((a)[2]), "r"((a)[3]), \
                   "r"((b)[0]), "r"((b)[1]))

// ---------------------------------------------------------------------------
// 1) Transpose: z [B,C,HW] -> z_out fp32 [B,HW,C]
// ---------------------------------------------------------------------------
__global__ void transpose_kernel(const float* __restrict__ z,
                                 float* __restrict__ zout) {
    __shared__ float tile[32][33];
    int b   = blockIdx.z;
    int hw0 = blockIdx.x * 32;
    int c0  = blockIdx.y * 32;
    const float* zp = z + (size_t)b * (Kn * HWn);
    size_t obase    = (size_t)b * (Kn * HWn);
    int tx = threadIdx.x, ty = threadIdx.y;
#pragma unroll
    for (int j = 0; j < 32; j += 8)
        tile[ty + j][tx] = zp[(c0 + ty + j) * HWn + hw0 + tx];
    __syncthreads();
#pragma unroll
    for (int j = 0; j < 32; j += 8)
        zout[obase + (size_t)(hw0 + ty + j) * Kn + c0 + tx] = tile[tx][ty + j];
}

// ---------------------------------------------------------------------------
// 2a) z row quantization (+ flag zero)
// ---------------------------------------------------------------------------
__global__ __launch_bounds__(256) void zquant_kernel(const float* __restrict__ zout) {
    int row  = (blockIdx.x * blockDim.x + threadIdx.x) >> 5;
    int lane = threadIdx.x & 31;
    const float4* zp = (const float4*)(zout + (size_t)row * Kn) + lane * 2;
    float4 v0 = zp[0], v1 = zp[1];
    float vals[8] = {v0.x, v0.y, v0.z, v0.w, v1.x, v1.y, v1.z, v1.w};
    float mx = 0.f;
#pragma unroll
    for (int j = 0; j < 8; j++) mx = fmaxf(mx, fabsf(vals[j]));
#pragma unroll
    for (int o = 16; o > 0; o >>= 1) mx = fmaxf(mx, __shfl_xor_sync(0xffffffffu, mx, o));
    mx = fmaxf(mx, 1e-20f);
    float zs = 127.f / mx;
    uint32_t p0 = 0, p1 = 0;
#pragma unroll
    for (int j = 0; j < 4; j++) {
        p0 |= ((uint32_t)(__float2int_rn(vals[j] * zs)     & 0xff)) << (8 * j);
        p1 |= ((uint32_t)(__float2int_rn(vals[4 + j] * zs) & 0xff)) << (8 * j);
    }
    *(uint2*)(g_qz + (size_t)row * Kn + lane * 8) = make_uint2(p0, p1);
    if (lane == 0) {
        g_izs[row]  = mx / 127.f;
        g_flag[row] = 0;
    }
}

// ---------------------------------------------------------------------------
// 2b) w row quantization + wnorm
// ---------------------------------------------------------------------------
__global__ __launch_bounds__(256) void wquant_kernel(const float* __restrict__ w) {
    if (blockIdx.x == 0 && threadIdx.x == 0) g_flag_count = 0;
    int row  = (blockIdx.x * blockDim.x + threadIdx.x) >> 5;
    int lane = threadIdx.x & 31;
    if (row >= Nn) return;
    const float4* wp = (const float4*)(w + (size_t)row * Kn) + lane * 2;
    float4 v0 = wp[0], v1 = wp[1];
    float vals[8] = {v0.x, v0.y, v0.z, v0.w, v1.x, v1.y, v1.z, v1.w};
    float mx = 0.f, ss = 0.f;
#pragma unroll
    for (int j = 0; j < 8; j++) { mx = fmaxf(mx, fabsf(vals[j])); ss += vals[j] * vals[j]; }
#pragma unroll
    for (int o = 16; o > 0; o >>= 1) {
        mx = fmaxf(mx, __shfl_xor_sync(0xffffffffu, mx, o));
        ss += __shfl_xor_sync(0xffffffffu, ss, o);
    }
    mx = fmaxf(mx, 1e-20f);
    float ws = 127.f / mx;
    uint32_t p0 = 0, p1 = 0;
#pragma unroll
    for (int j = 0; j < 4; j++) {
        p0 |= ((uint32_t)(__float2int_rn(vals[j] * ws)     & 0xff)) << (8 * j);
        p1 |= ((uint32_t)(__float2int_rn(vals[4 + j] * ws) & 0xff)) << (8 * j);
    }
    *(uint2*)(g_qw + (size_t)row * Kn + lane * 8) = make_uint2(p0, p1);
    if (lane == 0) {
        g_iws[row]   = mx / 127.f;
        g_wnorm[row] = 0.5f * ss;
    }
}

// ---------------------------------------------------------------------------
// 3) int8 IMMA GEMM: BM=64, N split in halves (grid 512), 3-stage B pipeline.
// ---------------------------------------------------------------------------
#define SM_A    0            // 16 KB
#define SM_B0   16384        // 3 x 32 KB stages
#define SM_MB   114688       // 6 mbarriers (3 full, 3 empty)
#define SMEM_BYTES 114944
#define SM_MV   0
#define SM_MI   24576

#define ROWSWZ(m, c) ((uint32_t)((m) * 256 + ((((c) & 8) | (((c) ^ ((m) & 7)) & 7)) << 4)))

__global__ void __launch_bounds__(256, 2) gemm_kernel() {
    extern __shared__ char smem[];
    const uint32_t sbase = smem_u32(smem);
    const int tid  = threadIdx.x;
    const int lane = tid & 31;
    const int wid  = tid >> 5;
    const int wm   = wid >> 2;       // 0..1
    const int wn   = wid & 3;        // 0..3
    const int lj   = lane >> 3;
    const int lr   = lane & 7;
    const int mblk  = blockIdx.x >> 1;
    const int nhalf = blockIdx.x & 1;
    const int m0    = mblk * 64;
    const int nbase = nhalf * (Nn / 2);

    const uint32_t mbF = sbase + SM_MB;        // full[s]  = mbF + s*8
    const uint32_t mbE = sbase + SM_MB + 24;   // empty[s] = mbE + s*8

    if (tid == 0) {
#pragma unroll
        for (int s = 0; s < 3; s++) {
            MBAR_INIT(mbF + s * 8, 256);
            MBAR_INIT(mbE + s * 8, 256);
        }
    }
    __syncthreads();

    // ---- prologue: A + B stages 0..2 ----
    {
        const char* srcA = (const char*)g_qz + (size_t)m0 * 256;
#pragma unroll
        for (int i = 0; i < 4; i++) {
            int f = tid + i * 256;
            int m = f >> 4, c = f & 15;
            cp_async16(sbase + SM_A + ROWSWZ(m, c), srcA + (size_t)m * 256 + c * 16);
        }
#pragma unroll
        for (int s = 0; s < 3; s++) {
            const char* srcB = (const char*)g_qw + ((size_t)nbase + s * 128) * 256;
            uint32_t dst = sbase + SM_B0 + s * 32768;
#pragma unroll
            for (int i = 0; i < 8; i++) {
                int f = tid + i * 256;
                int n = f >> 4, c = f & 15;
                cp_async16(dst + ROWSWZ(n, c), srcB + (size_t)n * 256 + c * 16);
            }
            CPASYNC_MBAR_ARRIVE(mbF + s * 8);
        }
    }

    float izv[4];
#pragma unroll
    for (int s = 0; s < 4; s++)
        izv[s] = __ldg(&g_izs[m0 + wm * 32 + (s >> 1) * 16 + (s & 1) * 8 + (lane >> 2)]);

    uint32_t aRow[2], aOff0[2];
#pragma unroll
    for (int mt = 0; mt < 2; mt++) {
        int ml = wm * 32 + mt * 16 + ((lj & 1) << 3) + lr;
        uint32_t cA0 = (uint32_t)(lj >> 1);
        aRow[mt]  = sbase + SM_A + (uint32_t)ml * 256;
        aOff0[mt] = (((cA0 & 8) | ((cA0 ^ (uint32_t)(ml & 7)) & 7)) << 4);
    }
    uint32_t bRel[2], bOff0[2];
#pragma unroll
    for (int p = 0; p < 2; p++) {
        int nl = wn * 32 + p * 16 + ((lj >> 1) << 3) + lr;
        uint32_t cB0 = (uint32_t)(lj & 1);
        bRel[p]  = (uint32_t)nl * 256;
        bOff0[p] = (((cB0 & 8) | ((cB0 ^ (uint32_t)(nl & 7)) & 7)) << 4);
    }

    float bv[4][6];
    int   bi[4][6];
#pragma unroll
    for (int s = 0; s < 4; s++)
#pragma unroll
        for (int e = 0; e < 6; e++) { bv[s][e] = -3.4e38f; bi[s][e] = 0; }

#define TOP6_INS(S, VAL, IDX)                                              \
    if ((VAL) > bv[S][5]) {                                                \
        float _cv = (VAL); int _ci = (IDX);                                \
        _Pragma("unroll")                                                  \
        for (int _q = 0; _q < 6; _q++) {                                   \
            if (_cv > bv[S][_q]) {                                         \
                float _tv = bv[S][_q]; int _ti = bi[S][_q];                \
                bv[S][_q] = _cv; bi[S][_q] = _ci; _cv = _tv; _ci = _ti;    \
            }                                                              \
        }                                                                  \
    }

    int stg = 0, par = 0;
    for (int t = 0; t < NTILE; t++) {
        const uint32_t cur = sbase + SM_B0 + (uint32_t)stg * 32768;
        const uint32_t mb_full  = mbF + stg * 8;
        const uint32_t mb_empty = mbE + stg * 8;

        mbar_wait(mb_full, (uint32_t)par);

        // prefetch epilogue constants (latency hidden under the k-loop)
        const int cbase = nbase + t * 128 + wn * 32 + 2 * (lane & 3);
        float wvv[4][2], iww[4][2];
#pragma unroll
        for (int f = 0; f < 4; f++) {
            float2 wv2 = __ldg((const float2*)(g_wnorm + cbase + f * 8));
            float2 iw2 = __ldg((const float2*)(g_iws  + cbase + f * 8));
            wvv[f][0] = wv2.x; wvv[f][1] = wv2.y;
            iww[f][0] = iw2.x; iww[f][1] = iw2.y;
        }

        uint32_t bRow[2];
        bRow[0] = cur + bRel[0];
        bRow[1] = cur + bRel[1];

        int C[2][4][4];
#pragma unroll
        for (int mt = 0; mt < 2; mt++)
#pragma unroll
            for (int f = 0; f < 4; f++)
#pragma unroll
                for (int e = 0; e < 4; e++) C[mt][f][e] = 0;

#pragma unroll
        for (int ks = 0; ks < 8; ks++) {
            const uint32_t kx = (uint32_t)(ks << 5);
            uint32_t a[2][4];
#pragma unroll
            for (int mt = 0; mt < 2; mt++) {
                LDSM_X4(a[mt][0], a[mt][1], a[mt][2], a[mt][3],
                        aRow[mt] + (aOff0[mt] ^ kx));
            }
            uint32_t b[4][2];
#pragma unroll
            for (int p = 0; p < 2; p++) {
                LDSM_X4(b[2 * p][0], b[2 * p][1], b[2 * p + 1][0], b[2 * p + 1][1],
                        bRow[p] + (bOff0[p] ^ kx));
            }
#pragma unroll
            for (int mt = 0; mt < 2; mt++)
#pragma unroll
                for (int f = 0; f < 4; f++)
                    IMMA16832(C[mt][f], a[mt], b[f]);
        }

        MBAR_ARRIVE(mb_empty);

        // epilogue overlaps other warps' MMA phase
#pragma unroll
        for (int f = 0; f < 4; f++) {
#pragma unroll
            for (int e = 0; e < 2; e++) {
                int col = cbase + f * 8 + e;
#pragma unroll
                for (int mt = 0; mt < 2; mt++) {
                    float s0 = __int2float_rn(C[mt][f][e])     * iww[f][e] * izv[mt * 2 + 0] - wvv[f][e];
                    float s1 = __int2float_rn(C[mt][f][2 + e]) * iww[f][e] * izv[mt * 2 + 1] - wvv[f][e];
                    TOP6_INS(mt * 2 + 0, s0, col);
                    TOP6_INS(mt * 2 + 1, s1, col);
                }
            }
        }

        // stage tile t+3 into this buffer once all threads released it
        if (t + 3 < NTILE) {
            mbar_wait(mb_empty, (uint32_t)par);
            const char* src = (const char*)g_qw + ((size_t)nbase + (t + 3) * 128) * 256;
#pragma unroll
            for (int i = 0; i < 8; i++) {
                int f = tid + i * 256;
                int n = f >> 4, c = f & 15;
                cp_async16(cur + ROWSWZ(n, c), src + (size_t)n * 256 + c * 16);
            }
            CPASYNC_MBAR_ARRIVE(mb_full);
        }

        if (++stg == 3) { stg = 0; par ^= 1; }
    }

    __syncthreads();

    // ---- cross-thread merge: 96 candidates/row -> top-16 for this half ----
    float* MV = (float*)(smem + SM_MV);   // [64][96]
    int*   MI = (int*)  (smem + SM_MI);
#pragma unroll
    for (int s = 0; s < 4; s++) {
        int row = wm * 32 + (s >> 1) * 16 + (s & 1) * 8 + (lane >> 2);
        int col = (wn * 4 + (lane & 3)) * 6;
#pragma unroll
        for (int e = 0; e < 6; e++) {
            MV[row * 96 + col + e] = bv[s][e];
            MI[row * 96 + col + e] = bi[s][e];
        }
    }
    __syncthreads();

    if (tid < 64) {
        int row = tid;
        float tv[NCAND];
        int   ti[NCAND];
#pragma unroll
        for (int e = 0; e < NCAND; e++) { tv[e] = -3.4e38f; ti[e] = 0; }
        for (int k = 0; k < 96; k++) {
            float v  = MV[row * 96 + k];
            int   ix = MI[row * 96 + k];
            if (v > tv[NCAND - 1]) {
                float cv = v; int ci = ix;
#pragma unroll
                for (int q = 0; q < NCAND; q++) {
                    if (cv > tv[q]) {
                        float xv = tv[q]; int xi = ti[q];
                        tv[q] = cv; ti[q] = ci; cv = xv; ci = xi;
                    }
                }
            }
        }
        int m = m0 + row;
#pragma unroll
        for (int e = 0; e < NCAND; e++) g_cand[m][nhalf][e] = ti[e];
        if (tv[0] - tv[NCAND - 1] <= CERT_WINDOW) {
            atomicOr(&g_flag[m], 1);
            int p = atomicAdd(&g_flag_count, 1);
            g_flag_list[p] = m;
        }
    }
}

// ---------------------------------------------------------------------------
// 4) Exact fp32 rescore of the 32 candidates (both halves), one warp per row
// ---------------------------------------------------------------------------
__global__ __launch_bounds__(256) void rescore_kernel(const float* __restrict__ zout,
                                                      const float* __restrict__ w,
                                                      float* __restrict__ idxf) {
    int m    = (blockIdx.x * blockDim.x + threadIdx.x) >> 5;
    int lane = threadIdx.x & 31;
    if (m >= Mn) return;
    if (g_flag[m]) return;

    float zr[8];
    const float* zp = zout + (size_t)m * Kn;
#pragma unroll
    for (int j = 0; j < 8; j++) zr[j] = zp[lane + 32 * j];

    const int* cp = g_cand[m][0];   // 32 contiguous entries
    float bestS = -3.4e38f;
    int   bestI = 0x7fffffff;
#pragma unroll 4
    for (int c = 0; c < 2 * NCAND; c++) {
        int idx = cp[c];
        const float* wp = w + (size_t)idx * Kn;
        float s = 0.f;
#pragma unroll
        for (int j = 0; j < 8; j++) s += zr[j] * wp[lane + 32 * j];
#pragma unroll
        for (int o = 16; o > 0; o >>= 1) s += __shfl_xor_sync(0xffffffffu, s, o);
        s -= g_wnorm[idx];
        if (s > bestS || (s == bestS && idx < bestI)) { bestS = s; bestI = idx; }
    }
    if (lane == 0) {
        g_bestidx[m] = bestI;
        idxf[m] = (float)bestI;
    }
}

// ---------------------------------------------------------------------------
// 5) Fallback full exact scan for flagged rows (expected ~0 rows)
// ---------------------------------------------------------------------------
__global__ __launch_bounds__(256) void fallback_kernel(const float* __restrict__ zout,
                                                       const float* __restrict__ w,
                                                       float* __restrict__ idxf) {
    __shared__ float sv[8];
    __shared__ int   si[8];
    int nflag = g_flag_count;
    int wi = threadIdx.x >> 5, lane = threadIdx.x & 31;
    for (int r = blockIdx.x; r < nflag; r += gridDim.x) {
        int m = g_flag_list[r];
        float zr[8];
        const float* zp = zout + (size_t)m * Kn;
#pragma unroll
        for (int j = 0; j < 8; j++) zr[j] = zp[lane + 32 * j];
        float bS = -3.4e38f;
        int   bI = 0x7fffffff;
        for (int n = wi; n < Nn; n += 8) {
            const float* wp = w + (size_t)n * Kn;
            float s = 0.f;
#pragma unroll
            for (int j = 0; j < 8; j++) s += zr[j] * wp[lane + 32 * j];
#pragma unroll
            for (int o = 16; o > 0; o >>= 1) s += __shfl_xor_sync(0xffffffffu, s, o);
            s -= g_wnorm[n];
            if (s > bS || (s == bS && n < bI)) { bS = s; bI = n; }
        }
        if (lane == 0) { sv[wi] = bS; si[wi] = bI; }
        __syncthreads();
        if (threadIdx.x == 0) {
            float bvv = sv[0]; int bii = si[0];
#pragma unroll
            for (int q = 1; q < 8; q++) {
                if (sv[q] > bvv || (sv[q] == bvv && si[q] < bii)) { bvv = sv[q]; bii = si[q]; }
            }
            g_bestidx[m] = bii;
            idxf[m] = (float)bii;
        }
        __syncthreads();
    }
}

// ---------------------------------------------------------------------------
// 6) Gather z_q
// ---------------------------------------------------------------------------
__global__ void gather_kernel(const float* __restrict__ w,
                              float* __restrict__ zq) {
    int t   = blockIdx.x * blockDim.x + threadIdx.x;
    int row = t >> 6;
    int c   = t & 63;
    int idx = g_bestidx[row];
    reinterpret_cast<float4*>(zq)[t] =
        reinterpret_cast<const float4*>(w)[(size_t)idx * 64 + c];
}

// ---------------------------------------------------------------------------
extern "C" void kernel_launch(void* const* d_in, const int* in_sizes, int n_in,
                              void* d_out, int out_size) {
    const float* z = (const float*)d_in[0];
    const float* w = (const float*)d_in[1];
    float* out   = (float*)d_out;
    float* z_out = out;
    float* z_q   = out + OUT_ZQ;
    float* idxf  = out + OUT_IDX;

    cudaFuncSetAttribute(gemm_kernel,
                         cudaFuncAttributeMaxDynamicSharedMemorySize, SMEM_BYTES);

    dim3 tt(32, 8);
    transpose_kernel<<<dim3(HWn / 32, Kn / 32, Bln), tt>>>(z, z_out);
    zquant_kernel<<<Mn / 8, 256>>>(z_out);
    wquant_kernel<<<Nn / 8, 256>>>(w);
    gemm_kernel<<<(Mn / 64) * 2, 256, SMEM_BYTES>>>();
    rescore_kernel<<<Mn / 8, 256>>>(z_out, w, idxf);
    fallback_kernel<<<128, 256>>>(z_out, w, idxf);
    gather_kernel<<<(Mn * Kn / 4) / 256, 256>>>(w, z_q);
}

// round 11
// speedup vs baseline: 1.0587x; 1.0587x over previous
#include <cuda_runtime.h>
#include <cuda_bf16.h>
#include <cstdint>

// ---------------------------------------------------------------------------
#define Mn  16384
#define Nn  8192
#define Kn  256
#define HWn 1024
#define Bln 16

#define OUT_ZQ  (Mn * Kn)
#define OUT_IDX (2 * Mn * Kn)

#define CERT_WINDOW 3.5f
#define NCAND 16
#define NTILE 32        // tiles per CTA (half of N, 128 cols each)

// ---------------------------------------------------------------------------
__device__ __align__(16) int8_t g_qz[Mn * Kn];
__device__ __align__(16) int8_t g_qw[Nn * Kn];
__device__ float g_izs[Mn];
__device__ float g_iws[Nn];
__device__ float g_wnorm[Nn];
__device__ int   g_bestidx[Mn];
__device__ int   g_cand[Mn][2][NCAND];
__device__ int   g_flag[Mn];
__device__ int   g_flag_list[Mn];
__device__ int   g_flag_count;

// ---------------------------------------------------------------------------
__device__ __forceinline__ uint32_t smem_u32(const void* p) {
    uint32_t a;
    asm("{ .reg .u64 t; cvta.to.shared.u64 t, %1; cvt.u32.u64 %0, t; }"
        : "=r"(a) : "l"(p));
    return a;
}
__device__ __forceinline__ void cp_async16(uint32_t dst, const void* src) {
    asm volatile("cp.async.cg.shared.global [%0], [%1], 16;"
                 :: "r"(dst), "l"(src) : "memory");
}
#define MBAR_INIT(a, c) \
    asm volatile("mbarrier.init.shared.b64 [%0], %1;" :: "r"(a), "r"(c) : "memory")
#define MBAR_ARRIVE(a) \
    asm volatile("mbarrier.arrive.shared.b64 _, [%0];" :: "r"(a) : "memory")
#define CPASYNC_MBAR_ARRIVE(a) \
    asm volatile("cp.async.mbarrier.arrive.noinc.shared.b64 [%0];" :: "r"(a) : "memory")

__device__ __forceinline__ void mbar_wait(uint32_t addr, uint32_t parity) {
    asm volatile(
        "{\n\t"
        ".reg .pred P;\n\t"
        "WL_%=:\n\t"
        "mbarrier.try_wait.parity.acquire.cta.shared::cta.b64 P, [%0], %1, 0x989680;\n\t"
        "@P bra.uni WD_%=;\n\t"
        "bra.uni WL_%=;\n\t"
        "WD_%=:\n\t"
        "}"
        :: "r"(addr), "r"(parity) : "memory");
}

#define LDSM_X4(r0, r1, r2, r3, a) \
    asm volatile("ldmatrix.sync.aligned.m8n8.x4.shared.b16 {%0,%1,%2,%3}, [%4];" \
                 : "=r"(r0), "=r"(r1), "=r"(r2), "=r"(r3) : "r"(a))

#define IMMA16832(c, a, b) \
    asm volatile("mma.sync.aligned.m16n8k32.row.col.s32.s8.s8.s32 " \
                 "{%0,%1,%2,%3}, {%4,%5,%6,%7}, {%8,%9}, {%0,%1,%2,%3};" \
                 : "+r"((c)[0]), "+r"((c)[1]), "+r"((c)[2]), "+r"((c)[3]) \
                 : "r"((a)[0]), "r"((a)[1]), "r"((a)[2]), "r"((a)[3]), \
                   "r"((b)[0]), "r"((b)[1]))

// ---------------------------------------------------------------------------
// 1) Transpose: z [B,C,HW] -> z_out fp32 [B,HW,C]
// ---------------------------------------------------------------------------
__global__ void transpose_kernel(const float* __restrict__ z,
                                 float* __restrict__ zout) {
    __shared__ float tile[32][33];
    int b   = blockIdx.z;
    int hw0 = blockIdx.x * 32;
    int c0  = blockIdx.y * 32;
    const float* zp = z + (size_t)b * (Kn * HWn);
    size_t obase    = (size_t)b * (Kn * HWn);
    int tx = threadIdx.x, ty = threadIdx.y;
#pragma unroll
    for (int j = 0; j < 32; j += 8)
        tile[ty + j][tx] = zp[(c0 + ty + j) * HWn + hw0 + tx];
    __syncthreads();
#pragma unroll
    for (int j = 0; j < 32; j += 8)
        zout[obase + (size_t)(hw0 + ty + j) * Kn + c0 + tx] = tile[tx][ty + j];
}

// ---------------------------------------------------------------------------
// 2a) z row quantization (+ flag zero)
// ---------------------------------------------------------------------------
__global__ __launch_bounds__(256) void zquant_kernel(const float* __restrict__ zout) {
    int row  = (blockIdx.x * blockDim.x + threadIdx.x) >> 5;
    int lane = threadIdx.x & 31;
    const float4* zp = (const float4*)(zout + (size_t)row * Kn) + lane * 2;
    float4 v0 = zp[0], v1 = zp[1];
    float vals[8] = {v0.x, v0.y, v0.z, v0.w, v1.x, v1.y, v1.z, v1.w};
    float mx = 0.f;
#pragma unroll
    for (int j = 0; j < 8; j++) mx = fmaxf(mx, fabsf(vals[j]));
#pragma unroll
    for (int o = 16; o > 0; o >>= 1) mx = fmaxf(mx, __shfl_xor_sync(0xffffffffu, mx, o));
    mx = fmaxf(mx, 1e-20f);
    float zs = 127.f / mx;
    uint32_t p0 = 0, p1 = 0;
#pragma unroll
    for (int j = 0; j < 4; j++) {
        p0 |= ((uint32_t)(__float2int_rn(vals[j] * zs)     & 0xff)) << (8 * j);
        p1 |= ((uint32_t)(__float2int_rn(vals[4 + j] * zs) & 0xff)) << (8 * j);
    }
    *(uint2*)(g_qz + (size_t)row * Kn + lane * 8) = make_uint2(p0, p1);
    if (lane == 0) {
        g_izs[row]  = mx / 127.f;
        g_flag[row] = 0;
    }
}

// ---------------------------------------------------------------------------
// 2b) w row quantization + wnorm
// ---------------------------------------------------------------------------
__global__ __launch_bounds__(256) void wquant_kernel(const float* __restrict__ w) {
    if (blockIdx.x == 0 && threadIdx.x == 0) g_flag_count = 0;
    int row  = (blockIdx.x * blockDim.x + threadIdx.x) >> 5;
    int lane = threadIdx.x & 31;
    if (row >= Nn) return;
    const float4* wp = (const float4*)(w + (size_t)row * Kn) + lane * 2;
    float4 v0 = wp[0], v1 = wp[1];
    float vals[8] = {v0.x, v0.y, v0.z, v0.w, v1.x, v1.y, v1.z, v1.w};
    float mx = 0.f, ss = 0.f;
#pragma unroll
    for (int j = 0; j < 8; j++) { mx = fmaxf(mx, fabsf(vals[j])); ss += vals[j] * vals[j]; }
#pragma unroll
    for (int o = 16; o > 0; o >>= 1) {
        mx = fmaxf(mx, __shfl_xor_sync(0xffffffffu, mx, o));
        ss += __shfl_xor_sync(0xffffffffu, ss, o);
    }
    mx = fmaxf(mx, 1e-20f);
    float ws = 127.f / mx;
    uint32_t p0 = 0, p1 = 0;
#pragma unroll
    for (int j = 0; j < 4; j++) {
        p0 |= ((uint32_t)(__float2int_rn(vals[j] * ws)     & 0xff)) << (8 * j);
        p1 |= ((uint32_t)(__float2int_rn(vals[4 + j] * ws) & 0xff)) << (8 * j);
    }
    *(uint2*)(g_qw + (size_t)row * Kn + lane * 8) = make_uint2(p0, p1);
    if (lane == 0) {
        g_iws[row]   = mx / 127.f;
        g_wnorm[row] = 0.5f * ss;
    }
}

// ---------------------------------------------------------------------------
// 3) int8 IMMA GEMM: BM=128, N-split 2 (grid 256), 2 CTAs/SM.
//    Halves B->SMEM staging traffic vs BM=64 (LDGSTS issue was ~45% of time).
//    8 warps 4(m)x2(n), warp tile 32x64, mbarrier 2-stage pipeline.
// ---------------------------------------------------------------------------
#define SM_A    0            // 32 KB
#define SM_B0   32768        // 32 KB
#define SM_B1   65536        // 32 KB
#define SM_MB   98304        // 4 mbarriers
#define SMEM_BYTES 98560
#define SM_MV   32768        // merge pool (post-loop, reuses B0)
#define SM_MI   49152

#define ROWSWZ(m, c) ((uint32_t)((m) * 256 + ((((c) & 8) | (((c) ^ ((m) & 7)) & 7)) << 4)))

__global__ void __launch_bounds__(256, 2) gemm_kernel() {
    extern __shared__ char smem[];
    const uint32_t sbase = smem_u32(smem);
    const int tid  = threadIdx.x;
    const int lane = tid & 31;
    const int wid  = tid >> 5;
    const int wm   = wid >> 1;       // 0..3
    const int wn   = wid & 1;        // 0..1
    const int lj   = lane >> 3;
    const int lr   = lane & 7;
    const int mblk  = blockIdx.x >> 1;
    const int nhalf = blockIdx.x & 1;
    const int m0    = mblk * 128;
    const int nbase = nhalf * (Nn / 2);

    const uint32_t mb_full0  = sbase + SM_MB + 0;
    const uint32_t mb_full1  = sbase + SM_MB + 8;
    const uint32_t mb_empty0 = sbase + SM_MB + 16;
    const uint32_t mb_empty1 = sbase + SM_MB + 24;

    if (tid == 0) {
        MBAR_INIT(mb_full0, 256);
        MBAR_INIT(mb_full1, 256);
        MBAR_INIT(mb_empty0, 256);
        MBAR_INIT(mb_empty1, 256);
    }
    __syncthreads();

    // ---- prologue: A (128x256) + B stages 0,1 ----
    {
        const char* srcA = (const char*)g_qz + (size_t)m0 * 256;
#pragma unroll
        for (int i = 0; i < 8; i++) {
            int f = tid + i * 256;
            int m = f >> 4, c = f & 15;
            cp_async16(sbase + SM_A + ROWSWZ(m, c), srcA + (size_t)m * 256 + c * 16);
        }
        const char* srcB = (const char*)g_qw + (size_t)nbase * 256;
#pragma unroll
        for (int i = 0; i < 8; i++) {
            int f = tid + i * 256;
            int n = f >> 4, c = f & 15;
            cp_async16(sbase + SM_B0 + ROWSWZ(n, c), srcB + (size_t)n * 256 + c * 16);
        }
        CPASYNC_MBAR_ARRIVE(mb_full0);
        srcB += 128 * 256;
#pragma unroll
        for (int i = 0; i < 8; i++) {
            int f = tid + i * 256;
            int n = f >> 4, c = f & 15;
            cp_async16(sbase + SM_B1 + ROWSWZ(n, c), srcB + (size_t)n * 256 + c * 16);
        }
        CPASYNC_MBAR_ARRIVE(mb_full1);
    }

    float izv[4];
#pragma unroll
    for (int s = 0; s < 4; s++)
        izv[s] = __ldg(&g_izs[m0 + wm * 32 + (s >> 1) * 16 + (s & 1) * 8 + (lane >> 2)]);

    uint32_t aRow[2], aOff0[2];
#pragma unroll
    for (int mt = 0; mt < 2; mt++) {
        int ml = wm * 32 + mt * 16 + ((lj & 1) << 3) + lr;
        uint32_t cA0 = (uint32_t)(lj >> 1);
        aRow[mt]  = sbase + SM_A + (uint32_t)ml * 256;
        aOff0[mt] = (((cA0 & 8) | ((cA0 ^ (uint32_t)(ml & 7)) & 7)) << 4);
    }
    uint32_t bRel[4], bOff0[4];
#pragma unroll
    for (int p = 0; p < 4; p++) {
        int nl = wn * 64 + p * 16 + ((lj >> 1) << 3) + lr;
        uint32_t cB0 = (uint32_t)(lj & 1);
        bRel[p]  = (uint32_t)nl * 256;
        bOff0[p] = (((cB0 & 8) | ((cB0 ^ (uint32_t)(nl & 7)) & 7)) << 4);
    }

    // top-4 per owned row (slot s = mt*2 + half)
    float bv[4][4];
    int   bi[4][4];
#pragma unroll
    for (int s = 0; s < 4; s++)
#pragma unroll
        for (int e = 0; e < 4; e++) { bv[s][e] = -3.4e38f; bi[s][e] = 0; }

#define TOP4_INS(S, VAL, IDX)                                              \
    if ((VAL) > bv[S][3]) {                                                \
        float _cv = (VAL); int _ci = (IDX);                                \
        _Pragma("unroll")                                                  \
        for (int _q = 0; _q < 4; _q++) {                                   \
            if (_cv > bv[S][_q]) {                                         \
                float _tv = bv[S][_q]; int _ti = bi[S][_q];                \
                bv[S][_q] = _cv; bi[S][_q] = _ci; _cv = _tv; _ci = _ti;    \
            }                                                              \
        }                                                                  \
    }

    for (int t = 0; t < NTILE; t++) {
        const int s = t & 1;
        const uint32_t par = (uint32_t)((t >> 1) & 1);
        const uint32_t cur = sbase + (s ? SM_B1 : SM_B0);
        const uint32_t mb_full  = s ? mb_full1  : mb_full0;
        const uint32_t mb_empty = s ? mb_empty1 : mb_empty0;

        mbar_wait(mb_full, par);

        int C[2][8][4];
#pragma unroll
        for (int mt = 0; mt < 2; mt++)
#pragma unroll
            for (int f = 0; f < 8; f++)
#pragma unroll
                for (int e = 0; e < 4; e++) C[mt][f][e] = 0;

#pragma unroll
        for (int ks = 0; ks < 8; ks++) {
            const uint32_t kx = (uint32_t)(ks << 5);
            uint32_t a[2][4];
#pragma unroll
            for (int mt = 0; mt < 2; mt++) {
                LDSM_X4(a[mt][0], a[mt][1], a[mt][2], a[mt][3],
                        aRow[mt] + (aOff0[mt] ^ kx));
            }
            uint32_t b[8][2];
#pragma unroll
            for (int p = 0; p < 4; p++) {
                LDSM_X4(b[2 * p][0], b[2 * p][1], b[2 * p + 1][0], b[2 * p + 1][1],
                        cur + bRel[p] + (bOff0[p] ^ kx));
            }
#pragma unroll
            for (int mt = 0; mt < 2; mt++)
#pragma unroll
                for (int f = 0; f < 8; f++)
                    IMMA16832(C[mt][f], a[mt], b[f]);
        }

        MBAR_ARRIVE(mb_empty);

        // epilogue (overlaps other warps' MMA phase)
        const int cbase = nbase + t * 128 + wn * 64 + 2 * (lane & 3);
#pragma unroll
        for (int f = 0; f < 8; f++) {
            float2 wv2 = __ldg((const float2*)(g_wnorm + cbase + f * 8));
            float2 iw2 = __ldg((const float2*)(g_iws  + cbase + f * 8));
#pragma unroll
            for (int e = 0; e < 2; e++) {
                int col = cbase + f * 8 + e;
                float wvv = e ? wv2.y : wv2.x;
                float iww = e ? iw2.y : iw2.x;
#pragma unroll
                for (int mt = 0; mt < 2; mt++) {
                    float s0 = __int2float_rn(C[mt][f][e])     * iww * izv[mt * 2 + 0] - wvv;
                    float s1 = __int2float_rn(C[mt][f][2 + e]) * iww * izv[mt * 2 + 1] - wvv;
                    TOP4_INS(mt * 2 + 0, s0, col);
                    TOP4_INS(mt * 2 + 1, s1, col);
                }
            }
        }

        // stage tile t+2 into this buffer once all threads released it
        if (t + 2 < NTILE) {
            mbar_wait(mb_empty, par);
            const char* src = (const char*)g_qw + ((size_t)nbase + (t + 2) * 128) * 256;
#pragma unroll
            for (int i = 0; i < 8; i++) {
                int f = tid + i * 256;
                int n = f >> 4, c = f & 15;
                cp_async16(cur + ROWSWZ(n, c), src + (size_t)n * 256 + c * 16);
            }
            CPASYNC_MBAR_ARRIVE(mb_full);
        }
    }

    __syncthreads();

    // ---- cross-thread merge: 32 candidates/row -> top-16 for this half ----
    float* MV = (float*)(smem + SM_MV);   // [128][32]
    int*   MI = (int*)  (smem + SM_MI);
#pragma unroll
    for (int s = 0; s < 4; s++) {
        int row = wm * 32 + (s >> 1) * 16 + (s & 1) * 8 + (lane >> 2);
        int col = wn * 16 + (lane & 3) * 4;
#pragma unroll
        for (int e = 0; e < 4; e++) {
            MV[row * 32 + col + e] = bv[s][e];
            MI[row * 32 + col + e] = bi[s][e];
        }
    }
    __syncthreads();

    if (tid < 128) {
        int row = tid;
        float tv[NCAND];
        int   ti[NCAND];
#pragma unroll
        for (int e = 0; e < NCAND; e++) { tv[e] = -3.4e38f; ti[e] = 0; }
        for (int k = 0; k < 32; k++) {
            float v  = MV[row * 32 + k];
            int   ix = MI[row * 32 + k];
            if (v > tv[NCAND - 1]) {
                float cv = v; int ci = ix;
#pragma unroll
                for (int q = 0; q < NCAND; q++) {
                    if (cv > tv[q]) {
                        float xv = tv[q]; int xi = ti[q];
                        tv[q] = cv; ti[q] = ci; cv = xv; ci = xi;
                    }
                }
            }
        }
        int m = m0 + row;
#pragma unroll
        for (int e = 0; e < NCAND; e++) g_cand[m][nhalf][e] = ti[e];
        if (tv[0] - tv[NCAND - 1] <= CERT_WINDOW) {
            atomicOr(&g_flag[m], 1);
            int p = atomicAdd(&g_flag_count, 1);
            g_flag_list[p] = m;
        }
    }
}

// ---------------------------------------------------------------------------
// 4) Exact fp32 rescore of the 32 candidates (both halves), one warp per row
// ---------------------------------------------------------------------------
__global__ __launch_bounds__(256) void rescore_kernel(const float* __restrict__ zout,
                                                      const float* __restrict__ w,
                                                      float* __restrict__ idxf) {
    int m    = (blockIdx.x * blockDim.x + threadIdx.x) >> 5;
    int lane = threadIdx.x & 31;
    if (m >= Mn) return;
    if (g_flag[m]) return;

    float zr[8];
    const float* zp = zout + (size_t)m * Kn;
#pragma unroll
    for (int j = 0; j < 8; j++) zr[j] = zp[lane + 32 * j];

    const int* cp = g_cand[m][0];   // 32 contiguous entries
    float bestS = -3.4e38f;
    int   bestI = 0x7fffffff;
#pragma unroll 4
    for (int c = 0; c < 2 * NCAND; c++) {
        int idx = cp[c];
        const float* wp = w + (size_t)idx * Kn;
        float s = 0.f;
#pragma unroll
        for (int j = 0; j < 8; j++) s += zr[j] * wp[lane + 32 * j];
#pragma unroll
        for (int o = 16; o > 0; o >>= 1) s += __shfl_xor_sync(0xffffffffu, s, o);
        s -= g_wnorm[idx];
        if (s > bestS || (s == bestS && idx < bestI)) { bestS = s; bestI = idx; }
    }
    if (lane == 0) {
        g_bestidx[m] = bestI;
        idxf[m] = (float)bestI;
    }
}

// ---------------------------------------------------------------------------
// 5) Fallback full exact scan for flagged rows (expected ~0 rows)
// ---------------------------------------------------------------------------
__global__ __launch_bounds__(256) void fallback_kernel(const float* __restrict__ zout,
                                                       const float* __restrict__ w,
                                                       float* __restrict__ idxf) {
    __shared__ float sv[8];
    __shared__ int   si[8];
    int nflag = g_flag_count;
    int wi = threadIdx.x >> 5, lane = threadIdx.x & 31;
    for (int r = blockIdx.x; r < nflag; r += gridDim.x) {
        int m = g_flag_list[r];
        float zr[8];
        const float* zp = zout + (size_t)m * Kn;
#pragma unroll
        for (int j = 0; j < 8; j++) zr[j] = zp[lane + 32 * j];
        float bS = -3.4e38f;
        int   bI = 0x7fffffff;
        for (int n = wi; n < Nn; n += 8) {
            const float* wp = w + (size_t)n * Kn;
            float s = 0.f;
#pragma unroll
            for (int j = 0; j < 8; j++) s += zr[j] * wp[lane + 32 * j];
#pragma unroll
            for (int o = 16; o > 0; o >>= 1) s += __shfl_xor_sync(0xffffffffu, s, o);
            s -= g_wnorm[n];
            if (s > bS || (s == bS && n < bI)) { bS = s; bI = n; }
        }
        if (lane == 0) { sv[wi] = bS; si[wi] = bI; }
        __syncthreads();
        if (threadIdx.x == 0) {
            float bvv = sv[0]; int bii = si[0];
#pragma unroll
            for (int q = 1; q < 8; q++) {
                if (sv[q] > bvv || (sv[q] == bvv && si[q] < bii)) { bvv = sv[q]; bii = si[q]; }
            }
            g_bestidx[m] = bii;
            idxf[m] = (float)bii;
        }
        __syncthreads();
    }
}

// ---------------------------------------------------------------------------
// 6) Gather z_q
// ---------------------------------------------------------------------------
__global__ void gather_kernel(const float* __restrict__ w,
                              float* __restrict__ zq) {
    int t   = blockIdx.x * blockDim.x + threadIdx.x;
    int row = t >> 6;
    int c   = t & 63;
    int idx = g_bestidx[row];
    reinterpret_cast<float4*>(zq)[t] =
        reinterpret_cast<const float4*>(w)[(size_t)idx * 64 + c];
}

// ---------------------------------------------------------------------------
extern "C" void kernel_launch(void* const* d_in, const int* in_sizes, int n_in,
                              void* d_out, int out_size) {
    const float* z = (const float*)d_in[0];
    const float* w = (const float*)d_in[1];
    float* out   = (float*)d_out;
    float* z_out = out;
    float* z_q   = out + OUT_ZQ;
    float* idxf  = out + OUT_IDX;

    cudaFuncSetAttribute(gemm_kernel,
                         cudaFuncAttributeMaxDynamicSharedMemorySize, SMEM_BYTES);

    dim3 tt(32, 8);
    transpose_kernel<<<dim3(HWn / 32, Kn / 32, Bln), tt>>>(z, z_out);
    zquant_kernel<<<Mn / 8, 256>>>(z_out);
    wquant_kernel<<<Nn / 8, 256>>>(w);
    gemm_kernel<<<(Mn / 128) * 2, 256, SMEM_BYTES>>>();
    rescore_kernel<<<Mn / 8, 256>>>(z_out, w, idxf);
    fallback_kernel<<<128, 256>>>(z_out, w, idxf);
    gather_kernel<<<(Mn * Kn / 4) / 256, 256>>>(w, z_q);
}

// round 12
// speedup vs baseline: 1.0630x; 1.0041x over previous
#include <cuda_runtime.h>
#include <cuda_bf16.h>
#include <cstdint>

// ---------------------------------------------------------------------------
#define Mn  16384
#define Nn  8192
#define Kn  256
#define HWn 1024
#define Bln 16

#define OUT_ZQ  (Mn * Kn)
#define OUT_IDX (2 * Mn * Kn)

#define CERT_WINDOW 3.5f
#define NCAND 16
#define NTILE 32        // tiles per CTA (half of N, 128 cols each)

// ---------------------------------------------------------------------------
__device__ __align__(16) int8_t g_qz[Mn * Kn];
__device__ __align__(16) int8_t g_qw[Nn * Kn];
__device__ float g_izs[Mn];
__device__ float g_iws[Nn];
__device__ float g_wnorm[Nn];
__device__ int   g_bestidx[Mn];
__device__ int   g_cand[Mn][2][NCAND];
__device__ int   g_flag[Mn];
__device__ int   g_flag_list[Mn];
__device__ int   g_flag_count;

// ---------------------------------------------------------------------------
__device__ __forceinline__ uint32_t smem_u32(const void* p) {
    uint32_t a;
    asm("{ .reg .u64 t; cvta.to.shared.u64 t, %1; cvt.u32.u64 %0, t; }"
        : "=r"(a) : "l"(p));
    return a;
}
__device__ __forceinline__ void cp_async16(uint32_t dst, const void* src) {
    asm volatile("cp.async.cg.shared.global [%0], [%1], 16;"
                 :: "r"(dst), "l"(src) : "memory");
}
#define MBAR_INIT(a, c) \
    asm volatile("mbarrier.init.shared.b64 [%0], %1;" :: "r"(a), "r"(c) : "memory")
#define MBAR_ARRIVE(a) \
    asm volatile("mbarrier.arrive.shared.b64 _, [%0];" :: "r"(a) : "memory")
#define CPASYNC_MBAR_ARRIVE(a) \
    asm volatile("cp.async.mbarrier.arrive.noinc.shared.b64 [%0];" :: "r"(a) : "memory")

__device__ __forceinline__ void mbar_wait(uint32_t addr, uint32_t parity) {
    asm volatile(
        "{\n\t"
        ".reg .pred P;\n\t"
        "WL_%=:\n\t"
        "mbarrier.try_wait.parity.acquire.cta.shared::cta.b64 P, [%0], %1, 0x989680;\n\t"
        "@P bra.uni WD_%=;\n\t"
        "bra.uni WL_%=;\n\t"
        "WD_%=:\n\t"
        "}"
        :: "r"(addr), "r"(parity) : "memory");
}

#define LDSM_X4(r0, r1, r2, r3, a) \
    asm volatile("ldmatrix.sync.aligned.m8n8.x4.shared.b16 {%0,%1,%2,%3}, [%4];" \
                 : "=r"(r0), "=r"(r1), "=r"(r2), "=r"(r3) : "r"(a))

#define IMMA16832(c, a, b) \
    asm volatile("mma.sync.aligned.m16n8k32.row.col.s32.s8.s8.s32 " \
                 "{%0,%1,%2,%3}, {%4,%5,%6,%7}, {%8,%9}, {%0,%1,%2,%3};" \
                 : "+r"((c)[0]), "+r"((c)[1]), "+r"((c)[2]), "+r"((c)[3]) \
                 : "r"((a)[0]), "r"((a)[1]), "r"((a)[2]), "r"((a)[3]), \
                   "r"((b)[0]), "r"((b)[1]))

// ---------------------------------------------------------------------------
// 1) Transpose: z [B,C,HW] -> z_out fp32 [B,HW,C]
// ---------------------------------------------------------------------------
__global__ void transpose_kernel(const float* __restrict__ z,
                                 float* __restrict__ zout) {
    __shared__ float tile[32][33];
    int b   = blockIdx.z;
    int hw0 = blockIdx.x * 32;
    int c0  = blockIdx.y * 32;
    const float* zp = z + (size_t)b * (Kn * HWn);
    size_t obase    = (size_t)b * (Kn * HWn);
    int tx = threadIdx.x, ty = threadIdx.y;
#pragma unroll
    for (int j = 0; j < 32; j += 8)
        tile[ty + j][tx] = zp[(c0 + ty + j) * HWn + hw0 + tx];
    __syncthreads();
#pragma unroll
    for (int j = 0; j < 32; j += 8)
        zout[obase + (size_t)(hw0 + ty + j) * Kn + c0 + tx] = tile[tx][ty + j];
}

// ---------------------------------------------------------------------------
// 2) Fused quantization: blocks [0, Mn/8) quantize z rows, the rest w rows.
// ---------------------------------------------------------------------------
__global__ __launch_bounds__(256) void zwquant_kernel(const float* __restrict__ zout,
                                                      const float* __restrict__ w) {
    int bid  = blockIdx.x;
    int lane = threadIdx.x & 31;
    if (bid < Mn / 8) {
        int row = bid * 8 + (threadIdx.x >> 5);
        const float4* zp = (const float4*)(zout + (size_t)row * Kn) + lane * 2;
        float4 v0 = zp[0], v1 = zp[1];
        float vals[8] = {v0.x, v0.y, v0.z, v0.w, v1.x, v1.y, v1.z, v1.w};
        float mx = 0.f;
#pragma unroll
        for (int j = 0; j < 8; j++) mx = fmaxf(mx, fabsf(vals[j]));
#pragma unroll
        for (int o = 16; o > 0; o >>= 1) mx = fmaxf(mx, __shfl_xor_sync(0xffffffffu, mx, o));
        mx = fmaxf(mx, 1e-20f);
        float zs = 127.f / mx;
        uint32_t p0 = 0, p1 = 0;
#pragma unroll
        for (int j = 0; j < 4; j++) {
            p0 |= ((uint32_t)(__float2int_rn(vals[j] * zs)     & 0xff)) << (8 * j);
            p1 |= ((uint32_t)(__float2int_rn(vals[4 + j] * zs) & 0xff)) << (8 * j);
        }
        *(uint2*)(g_qz + (size_t)row * Kn + lane * 8) = make_uint2(p0, p1);
        if (lane == 0) {
            g_izs[row]  = mx / 127.f;
            g_flag[row] = 0;
        }
    } else {
        if (bid == Mn / 8 && threadIdx.x == 0) g_flag_count = 0;
        int row = (bid - Mn / 8) * 8 + (threadIdx.x >> 5);
        if (row >= Nn) return;
        const float4* wp = (const float4*)(w + (size_t)row * Kn) + lane * 2;
        float4 v0 = wp[0], v1 = wp[1];
        float vals[8] = {v0.x, v0.y, v0.z, v0.w, v1.x, v1.y, v1.z, v1.w};
        float mx = 0.f, ss = 0.f;
#pragma unroll
        for (int j = 0; j < 8; j++) { mx = fmaxf(mx, fabsf(vals[j])); ss += vals[j] * vals[j]; }
#pragma unroll
        for (int o = 16; o > 0; o >>= 1) {
            mx = fmaxf(mx, __shfl_xor_sync(0xffffffffu, mx, o));
            ss += __shfl_xor_sync(0xffffffffu, ss, o);
        }
        mx = fmaxf(mx, 1e-20f);
        float ws = 127.f / mx;
        uint32_t p0 = 0, p1 = 0;
#pragma unroll
        for (int j = 0; j < 4; j++) {
            p0 |= ((uint32_t)(__float2int_rn(vals[j] * ws)     & 0xff)) << (8 * j);
            p1 |= ((uint32_t)(__float2int_rn(vals[4 + j] * ws) & 0xff)) << (8 * j);
        }
        *(uint2*)(g_qw + (size_t)row * Kn + lane * 8) = make_uint2(p0, p1);
        if (lane == 0) {
            g_iws[row]   = mx / 127.f;
            g_wnorm[row] = 0.5f * ss;
        }
    }
}

// ---------------------------------------------------------------------------
// 3) int8 IMMA GEMM: BM=128, N-split 2 (grid 256), 2 CTAs/SM.
//    B stages split per n-half with independent barriers: the two wn warp
//    groups run as decoupled pipelines (group skew covers epilogue gaps).
//    Warp map: wm = wid&3 (m), wn = wid>>2 (n) -> each SMSP gets one warp
//    of each group per CTA.
// ---------------------------------------------------------------------------
#define SM_A    0            // 32 KB
#define SM_B0   32768        // 32 KB (half h at +h*16384)
#define SM_B1   65536        // 32 KB
#define SM_MB   98304        // barriers: fullH[2][2], emptyH[2][2], afull
#define SMEM_BYTES 98688
#define SM_MV   32768        // merge pool (post-loop, reuses B0)
#define SM_MI   49152

#define ROWSWZ(m, c) ((uint32_t)((m) * 256 + ((((c) & 8) | (((c) ^ ((m) & 7)) & 7)) << 4)))

__global__ void __launch_bounds__(256, 2) gemm_kernel() {
    extern __shared__ char smem[];
    const uint32_t sbase = smem_u32(smem);
    const int tid  = threadIdx.x;
    const int lane = tid & 31;
    const int wid  = tid >> 5;
    const int wm   = wid & 3;        // 0..3 (m)
    const int wn   = wid >> 2;       // 0..1 (n group)
    const int lj   = lane >> 3;
    const int lr   = lane & 7;
    const int mblk  = blockIdx.x >> 1;
    const int nhalf = blockIdx.x & 1;
    const int m0    = mblk * 128;
    const int nbase = nhalf * (Nn / 2);

    // barrier layout: fullH[s][h] = SM_MB + (s*2+h)*8 ; emptyH = +32 ; afull = +64
    const uint32_t mbF   = sbase + SM_MB;
    const uint32_t mbE   = sbase + SM_MB + 32;
    const uint32_t mbA   = sbase + SM_MB + 64;

    if (tid == 0) {
#pragma unroll
        for (int i = 0; i < 4; i++) {
            MBAR_INIT(mbF + i * 8, 128);
            MBAR_INIT(mbE + i * 8, 128);
        }
        MBAR_INIT(mbA, 256);
    }
    __syncthreads();

    // ---- prologue: A (all threads) + B halves (own group's half, t0 & t1) ----
    {
        const char* srcA = (const char*)g_qz + (size_t)m0 * 256;
#pragma unroll
        for (int i = 0; i < 8; i++) {
            int f = tid + i * 256;
            int m = f >> 4, c = f & 15;
            cp_async16(sbase + SM_A + ROWSWZ(m, c), srcA + (size_t)m * 256 + c * 16);
        }
        CPASYNC_MBAR_ARRIVE(mbA);

        // group h stages rows [h*64, h*64+64) of each B tile; 1024 chunks
        // per half -> 8 per thread of the 128-thread group
        const int gt = (wn * 128 + tid) & 127;   // thread index within group = tid%128? no:
        // group membership: warps 0-3 => wn0 threads tid 0..127; warps 4-7 => wn1 tid 128..255
        const int lt = tid & 127;                // 0..127 within group
#pragma unroll
        for (int s = 0; s < 2; s++) {
            const char* srcB = (const char*)g_qw +
                ((size_t)nbase + s * 128 + wn * 64) * 256;
            uint32_t dst = sbase + (s ? SM_B1 : SM_B0) + wn * 16384;
#pragma unroll
            for (int i = 0; i < 8; i++) {
                int f = lt + i * 128;
                int n = f >> 4, c = f & 15;   // n = 0..63 local
                cp_async16(dst + ROWSWZ(n, c), srcB + (size_t)n * 256 + c * 16);
            }
            CPASYNC_MBAR_ARRIVE(mbF + (s * 2 + wn) * 8);
        }
        (void)gt;
    }

    float izv[4];
#pragma unroll
    for (int s = 0; s < 4; s++)
        izv[s] = __ldg(&g_izs[m0 + wm * 32 + (s >> 1) * 16 + (s & 1) * 8 + (lane >> 2)]);

    uint32_t aRow[2], aOff0[2];
#pragma unroll
    for (int mt = 0; mt < 2; mt++) {
        int ml = wm * 32 + mt * 16 + ((lj & 1) << 3) + lr;
        uint32_t cA0 = (uint32_t)(lj >> 1);
        aRow[mt]  = sbase + SM_A + (uint32_t)ml * 256;
        aOff0[mt] = (((cA0 & 8) | ((cA0 ^ (uint32_t)(ml & 7)) & 7)) << 4);
    }
    // B rows local to this group's half (local n 0..63)
    uint32_t bRel[4], bOff0[4];
#pragma unroll
    for (int p = 0; p < 4; p++) {
        int nl = p * 16 + ((lj >> 1) << 3) + lr;   // 0..63 local
        uint32_t cB0 = (uint32_t)(lj & 1);
        bRel[p]  = (uint32_t)nl * 256 + (uint32_t)wn * 16384;
        bOff0[p] = (((cB0 & 8) | ((cB0 ^ (uint32_t)(nl & 7)) & 7)) << 4);
    }

    float bv[4][4];
    int   bi[4][4];
#pragma unroll
    for (int s = 0; s < 4; s++)
#pragma unroll
        for (int e = 0; e < 4; e++) { bv[s][e] = -3.4e38f; bi[s][e] = 0; }

#define TOP4_INS(S, VAL, IDX)                                              \
    if ((VAL) > bv[S][3]) {                                                \
        float _cv = (VAL); int _ci = (IDX);                                \
        _Pragma("unroll")                                                  \
        for (int _q = 0; _q < 4; _q++) {                                   \
            if (_cv > bv[S][_q]) {                                         \
                float _tv = bv[S][_q]; int _ti = bi[S][_q];                \
                bv[S][_q] = _cv; bi[S][_q] = _ci; _cv = _tv; _ci = _ti;    \
            }                                                              \
        }                                                                  \
    }

    const int lt = tid & 127;
    bool awaited = false;
    for (int t = 0; t < NTILE; t++) {
        const int s = t & 1;
        const uint32_t par = (uint32_t)((t >> 1) & 1);
        const uint32_t cur = sbase + (s ? SM_B1 : SM_B0);
        const uint32_t mb_full  = mbF + (s * 2 + wn) * 8;
        const uint32_t mb_empty = mbE + (s * 2 + wn) * 8;

        mbar_wait(mb_full, par);
        if (!awaited) { mbar_wait(mbA, 0); awaited = true; }

        int C[2][8][4];
#pragma unroll
        for (int mt = 0; mt < 2; mt++)
#pragma unroll
            for (int f = 0; f < 8; f++)
#pragma unroll
                for (int e = 0; e < 4; e++) C[mt][f][e] = 0;

#pragma unroll
        for (int ks = 0; ks < 8; ks++) {
            const uint32_t kx = (uint32_t)(ks << 5);
            uint32_t a[2][4];
#pragma unroll
            for (int mt = 0; mt < 2; mt++) {
                LDSM_X4(a[mt][0], a[mt][1], a[mt][2], a[mt][3],
                        aRow[mt] + (aOff0[mt] ^ kx));
            }
            uint32_t b[8][2];
#pragma unroll
            for (int p = 0; p < 4; p++) {
                LDSM_X4(b[2 * p][0], b[2 * p][1], b[2 * p + 1][0], b[2 * p + 1][1],
                        cur + bRel[p] + (bOff0[p] ^ kx));
            }
#pragma unroll
            for (int mt = 0; mt < 2; mt++)
#pragma unroll
                for (int f = 0; f < 8; f++)
                    IMMA16832(C[mt][f], a[mt], b[f]);
        }

        MBAR_ARRIVE(mb_empty);

        // epilogue (overlaps the other group's / CTA's MMA phase)
        const int cbase = nbase + t * 128 + wn * 64 + 2 * (lane & 3);
#pragma unroll
        for (int f = 0; f < 8; f++) {
            float2 wv2 = __ldg((const float2*)(g_wnorm + cbase + f * 8));
            float2 iw2 = __ldg((const float2*)(g_iws  + cbase + f * 8));
#pragma unroll
            for (int e = 0; e < 2; e++) {
                int col = cbase + f * 8 + e;
                float wvv = e ? wv2.y : wv2.x;
                float iww = e ? iw2.y : iw2.x;
#pragma unroll
                for (int mt = 0; mt < 2; mt++) {
                    float s0 = __int2float_rn(C[mt][f][e])     * iww * izv[mt * 2 + 0] - wvv;
                    float s1 = __int2float_rn(C[mt][f][2 + e]) * iww * izv[mt * 2 + 1] - wvv;
                    TOP4_INS(mt * 2 + 0, s0, col);
                    TOP4_INS(mt * 2 + 1, s1, col);
                }
            }
        }

        // stage own half of tile t+2 once this group released the buffer
        if (t + 2 < NTILE) {
            mbar_wait(mb_empty, par);
            const char* src = (const char*)g_qw +
                ((size_t)nbase + (t + 2) * 128 + wn * 64) * 256;
#pragma unroll
            for (int i = 0; i < 8; i++) {
                int f = lt + i * 128;
                int n = f >> 4, c = f & 15;
                cp_async16(cur + (uint32_t)wn * 16384 + ROWSWZ(n, c),
                           src + (size_t)n * 256 + c * 16);
            }
            CPASYNC_MBAR_ARRIVE(mb_full);
        }
    }

    __syncthreads();

    // ---- cross-thread merge: 32 candidates/row -> top-16 for this half ----
    float* MV = (float*)(smem + SM_MV);   // [128][32]
    int*   MI = (int*)  (smem + SM_MI);
#pragma unroll
    for (int s = 0; s < 4; s++) {
        int row = wm * 32 + (s >> 1) * 16 + (s & 1) * 8 + (lane >> 2);
        int col = wn * 16 + (lane & 3) * 4;
#pragma unroll
        for (int e = 0; e < 4; e++) {
            MV[row * 32 + col + e] = bv[s][e];
            MI[row * 32 + col + e] = bi[s][e];
        }
    }
    __syncthreads();

    if (tid < 128) {
        int row = tid;
        float tv[NCAND];
        int   ti[NCAND];
#pragma unroll
        for (int e = 0; e < NCAND; e++) { tv[e] = -3.4e38f; ti[e] = 0; }
        for (int k = 0; k < 32; k++) {
            float v  = MV[row * 32 + k];
            int   ix = MI[row * 32 + k];
            if (v > tv[NCAND - 1]) {
                float cv = v; int ci = ix;
#pragma unroll
                for (int q = 0; q < NCAND; q++) {
                    if (cv > tv[q]) {
                        float xv = tv[q]; int xi = ti[q];
                        tv[q] = cv; ti[q] = ci; cv = xv; ci = xi;
                    }
                }
            }
        }
        int m = m0 + row;
#pragma unroll
        for (int e = 0; e < NCAND; e++) g_cand[m][nhalf][e] = ti[e];
        if (tv[0] - tv[NCAND - 1] <= CERT_WINDOW) {
            atomicOr(&g_flag[m], 1);
            int p = atomicAdd(&g_flag_count, 1);
            g_flag_list[p] = m;
        }
    }
}

// ---------------------------------------------------------------------------
// 4) Exact fp32 rescore of the 32 candidates + fused z_q gather
// ---------------------------------------------------------------------------
__global__ __launch_bounds__(256) void rescore_kernel(const float* __restrict__ zout,
                                                      const float* __restrict__ w,
                                                      float* __restrict__ idxf,
                                                      float* __restrict__ zq) {
    int m    = (blockIdx.x * blockDim.x + threadIdx.x) >> 5;
    int lane = threadIdx.x & 31;
    if (m >= Mn) return;
    if (g_flag[m]) return;

    float zr[8];
    const float* zp = zout + (size_t)m * Kn;
#pragma unroll
    for (int j = 0; j < 8; j++) zr[j] = zp[lane + 32 * j];

    const int* cp = g_cand[m][0];   // 32 contiguous entries
    float bestS = -3.4e38f;
    int   bestI = 0x7fffffff;
#pragma unroll 4
    for (int c = 0; c < 2 * NCAND; c++) {
        int idx = cp[c];
        const float* wp = w + (size_t)idx * Kn;
        float s = 0.f;
#pragma unroll
        for (int j = 0; j < 8; j++) s += zr[j] * wp[lane + 32 * j];
#pragma unroll
        for (int o = 16; o > 0; o >>= 1) s += __shfl_xor_sync(0xffffffffu, s, o);
        s -= g_wnorm[idx];
        if (s > bestS || (s == bestS && idx < bestI)) { bestS = s; bestI = idx; }
    }
    if (lane == 0) {
        g_bestidx[m] = bestI;
        idxf[m] = (float)bestI;
    }
    // fused gather: z_q[m,:] = w[bestI,:]  (bestI identical on all lanes)
    const float4* src = (const float4*)(w + (size_t)bestI * Kn);
    float4* dst = (float4*)(zq + (size_t)m * Kn);
    dst[lane]      = src[lane];
    dst[lane + 32] = src[lane + 32];
}

// ---------------------------------------------------------------------------
// 5) Fallback full exact scan for flagged rows (+ fused z_q gather)
// ---------------------------------------------------------------------------
__global__ __launch_bounds__(256) void fallback_kernel(const float* __restrict__ zout,
                                                       const float* __restrict__ w,
                                                       float* __restrict__ idxf,
                                                       float* __restrict__ zq) {
    __shared__ float sv[8];
    __shared__ int   si[8];
    __shared__ int   sbest;
    int nflag = g_flag_count;
    int wi = threadIdx.x >> 5, lane = threadIdx.x & 31;
    for (int r = blockIdx.x; r < nflag; r += gridDim.x) {
        int m = g_flag_list[r];
        float zr[8];
        const float* zp = zout + (size_t)m * Kn;
#pragma unroll
        for (int j = 0; j < 8; j++) zr[j] = zp[lane + 32 * j];
        float bS = -3.4e38f;
        int   bI = 0x7fffffff;
        for (int n = wi; n < Nn; n += 8) {
            const float* wp = w + (size_t)n * Kn;
            float s = 0.f;
#pragma unroll
            for (int j = 0; j < 8; j++) s += zr[j] * wp[lane + 32 * j];
#pragma unroll
            for (int o = 16; o > 0; o >>= 1) s += __shfl_xor_sync(0xffffffffu, s, o);
            s -= g_wnorm[n];
            if (s > bS || (s == bS && n < bI)) { bS = s; bI = n; }
        }
        if (lane == 0) { sv[wi] = bS; si[wi] = bI; }
        __syncthreads();
        if (threadIdx.x == 0) {
            float bvv = sv[0]; int bii = si[0];
#pragma unroll
            for (int q = 1; q < 8; q++) {
                if (sv[q] > bvv || (sv[q] == bvv && si[q] < bii)) { bvv = sv[q]; bii = si[q]; }
            }
            g_bestidx[m] = bii;
            idxf[m] = (float)bii;
            sbest = bii;
        }
        __syncthreads();
        int bii = sbest;
        // fused gather: 64 threads write the 64 float4s of z_q row m
        if (threadIdx.x < 64) {
            ((float4*)(zq + (size_t)m * Kn))[threadIdx.x] =
                ((const float4*)(w + (size_t)bii * Kn))[threadIdx.x];
        }
        __syncthreads();
    }
}

// ---------------------------------------------------------------------------
extern "C" void kernel_launch(void* const* d_in, const int* in_sizes, int n_in,
                              void* d_out, int out_size) {
    const float* z = (const float*)d_in[0];
    const float* w = (const float*)d_in[1];
    float* out   = (float*)d_out;
    float* z_out = out;
    float* z_q   = out + OUT_ZQ;
    float* idxf  = out + OUT_IDX;

    cudaFuncSetAttribute(gemm_kernel,
                         cudaFuncAttributeMaxDynamicSharedMemorySize, SMEM_BYTES);

    dim3 tt(32, 8);
    transpose_kernel<<<dim3(HWn / 32, Kn / 32, Bln), tt>>>(z, z_out);
    zwquant_kernel<<<Mn / 8 + Nn / 8, 256>>>(z_out, w);
    gemm_kernel<<<(Mn / 128) * 2, 256, SMEM_BYTES>>>();
    rescore_kernel<<<Mn / 8, 256>>>(z_out, w, idxf, z_q);
    fallback_kernel<<<128, 256>>>(z_out, w, idxf, z_q);
}

// round 13
// speedup vs baseline: 1.0989x; 1.0338x over previous
#include <cuda_runtime.h>
#include <cuda_bf16.h>
#include <cstdint>

// ---------------------------------------------------------------------------
#define Mn  16384
#define Nn  8192
#define Kn  256
#define HWn 1024
#define Bln 16

#define OUT_ZQ  (Mn * Kn)
#define OUT_IDX (2 * Mn * Kn)

#define CERT_WINDOW 3.5f
#define NCAND 16
#define NTILE 32        // tiles per CTA (half of N, 128 cols each)

// ---------------------------------------------------------------------------
__device__ __align__(16) int8_t g_qz[Mn * Kn];
__device__ __align__(16) int8_t g_qw[Nn * Kn];
__device__ float g_izs[Mn];
__device__ float g_iws[Nn];
__device__ float g_wnorm[Nn];
__device__ int   g_bestidx[Mn];
__device__ int   g_cand[Mn][2][NCAND];
__device__ float g_candv[Mn][2][NCAND];
__device__ int   g_flag[Mn];
__device__ int   g_flag_list[Mn];
__device__ int   g_flag_count;

// ---------------------------------------------------------------------------
__device__ __forceinline__ uint32_t smem_u32(const void* p) {
    uint32_t a;
    asm("{ .reg .u64 t; cvta.to.shared.u64 t, %1; cvt.u32.u64 %0, t; }"
        : "=r"(a) : "l"(p));
    return a;
}
__device__ __forceinline__ void cp_async16(uint32_t dst, const void* src) {
    asm volatile("cp.async.cg.shared.global [%0], [%1], 16;"
                 :: "r"(dst), "l"(src) : "memory");
}
#define MBAR_INIT(a, c) \
    asm volatile("mbarrier.init.shared.b64 [%0], %1;" :: "r"(a), "r"(c) : "memory")
#define MBAR_ARRIVE(a) \
    asm volatile("mbarrier.arrive.shared.b64 _, [%0];" :: "r"(a) : "memory")
#define CPASYNC_MBAR_ARRIVE(a) \
    asm volatile("cp.async.mbarrier.arrive.noinc.shared.b64 [%0];" :: "r"(a) : "memory")

__device__ __forceinline__ void mbar_wait(uint32_t addr, uint32_t parity) {
    asm volatile(
        "{\n\t"
        ".reg .pred P;\n\t"
        "WL_%=:\n\t"
        "mbarrier.try_wait.parity.acquire.cta.shared::cta.b64 P, [%0], %1, 0x989680;\n\t"
        "@P bra.uni WD_%=;\n\t"
        "bra.uni WL_%=;\n\t"
        "WD_%=:\n\t"
        "}"
        :: "r"(addr), "r"(parity) : "memory");
}

#define LDSM_X4(r0, r1, r2, r3, a) \
    asm volatile("ldmatrix.sync.aligned.m8n8.x4.shared.b16 {%0,%1,%2,%3}, [%4];" \
                 : "=r"(r0), "=r"(r1), "=r"(r2), "=r"(r3) : "r"(a))

#define IMMA16832(c, a, b) \
    asm volatile("mma.sync.aligned.m16n8k32.row.col.s32.s8.s8.s32 " \
                 "{%0,%1,%2,%3}, {%4,%5,%6,%7}, {%8,%9}, {%0,%1,%2,%3};" \
                 : "+r"((c)[0]), "+r"((c)[1]), "+r"((c)[2]), "+r"((c)[3]) \
                 : "r"((a)[0]), "r"((a)[1]), "r"((a)[2]), "r"((a)[3]), \
                   "r"((b)[0]), "r"((b)[1]))

// ---------------------------------------------------------------------------
// 1) Transpose: z [B,C,HW] -> z_out fp32 [B,HW,C]
// ---------------------------------------------------------------------------
__global__ void transpose_kernel(const float* __restrict__ z,
                                 float* __restrict__ zout) {
    __shared__ float tile[32][33];
    int b   = blockIdx.z;
    int hw0 = blockIdx.x * 32;
    int c0  = blockIdx.y * 32;
    const float* zp = z + (size_t)b * (Kn * HWn);
    size_t obase    = (size_t)b * (Kn * HWn);
    int tx = threadIdx.x, ty = threadIdx.y;
#pragma unroll
    for (int j = 0; j < 32; j += 8)
        tile[ty + j][tx] = zp[(c0 + ty + j) * HWn + hw0 + tx];
    __syncthreads();
#pragma unroll
    for (int j = 0; j < 32; j += 8)
        zout[obase + (size_t)(hw0 + ty + j) * Kn + c0 + tx] = tile[tx][ty + j];
}

// ---------------------------------------------------------------------------
// 2) Fused quantization: blocks [0, Mn/8) quantize z rows, the rest w rows.
// ---------------------------------------------------------------------------
__global__ __launch_bounds__(256) void zwquant_kernel(const float* __restrict__ zout,
                                                      const float* __restrict__ w) {
    int bid  = blockIdx.x;
    int lane = threadIdx.x & 31;
    if (bid < Mn / 8) {
        int row = bid * 8 + (threadIdx.x >> 5);
        const float4* zp = (const float4*)(zout + (size_t)row * Kn) + lane * 2;
        float4 v0 = zp[0], v1 = zp[1];
        float vals[8] = {v0.x, v0.y, v0.z, v0.w, v1.x, v1.y, v1.z, v1.w};
        float mx = 0.f;
#pragma unroll
        for (int j = 0; j < 8; j++) mx = fmaxf(mx, fabsf(vals[j]));
#pragma unroll
        for (int o = 16; o > 0; o >>= 1) mx = fmaxf(mx, __shfl_xor_sync(0xffffffffu, mx, o));
        mx = fmaxf(mx, 1e-20f);
        float zs = 127.f / mx;
        uint32_t p0 = 0, p1 = 0;
#pragma unroll
        for (int j = 0; j < 4; j++) {
            p0 |= ((uint32_t)(__float2int_rn(vals[j] * zs)     & 0xff)) << (8 * j);
            p1 |= ((uint32_t)(__float2int_rn(vals[4 + j] * zs) & 0xff)) << (8 * j);
        }
        *(uint2*)(g_qz + (size_t)row * Kn + lane * 8) = make_uint2(p0, p1);
        if (lane == 0) {
            g_izs[row]  = mx / 127.f;
            g_flag[row] = 0;
        }
    } else {
        if (bid == Mn / 8 && threadIdx.x == 0) g_flag_count = 0;
        int row = (bid - Mn / 8) * 8 + (threadIdx.x >> 5);
        if (row >= Nn) return;
        const float4* wp = (const float4*)(w + (size_t)row * Kn) + lane * 2;
        float4 v0 = wp[0], v1 = wp[1];
        float vals[8] = {v0.x, v0.y, v0.z, v0.w, v1.x, v1.y, v1.z, v1.w};
        float mx = 0.f, ss = 0.f;
#pragma unroll
        for (int j = 0; j < 8; j++) { mx = fmaxf(mx, fabsf(vals[j])); ss += vals[j] * vals[j]; }
#pragma unroll
        for (int o = 16; o > 0; o >>= 1) {
            mx = fmaxf(mx, __shfl_xor_sync(0xffffffffu, mx, o));
            ss += __shfl_xor_sync(0xffffffffu, ss, o);
        }
        mx = fmaxf(mx, 1e-20f);
        float ws = 127.f / mx;
        uint32_t p0 = 0, p1 = 0;
#pragma unroll
        for (int j = 0; j < 4; j++) {
            p0 |= ((uint32_t)(__float2int_rn(vals[j] * ws)     & 0xff)) << (8 * j);
            p1 |= ((uint32_t)(__float2int_rn(vals[4 + j] * ws) & 0xff)) << (8 * j);
        }
        *(uint2*)(g_qw + (size_t)row * Kn + lane * 8) = make_uint2(p0, p1);
        if (lane == 0) {
            g_iws[row]   = mx / 127.f;
            g_wnorm[row] = 0.5f * ss;
        }
    }
}

// ---------------------------------------------------------------------------
// 3) int8 IMMA GEMM: BM=128, N-split 2 (grid 256), 2 CTAs/SM, per-half
//    decoupled B pipelines.
// ---------------------------------------------------------------------------
#define SM_A    0            // 32 KB
#define SM_B0   32768        // 32 KB (half h at +h*16384)
#define SM_B1   65536        // 32 KB
#define SM_MB   98304        // barriers: fullH[2][2], emptyH[2][2], afull
#define SMEM_BYTES 98688
#define SM_MV   32768        // merge pool (post-loop, reuses B0)
#define SM_MI   49152

#define ROWSWZ(m, c) ((uint32_t)((m) * 256 + ((((c) & 8) | (((c) ^ ((m) & 7)) & 7)) << 4)))

__global__ void __launch_bounds__(256, 2) gemm_kernel() {
    extern __shared__ char smem[];
    const uint32_t sbase = smem_u32(smem);
    const int tid  = threadIdx.x;
    const int lane = tid & 31;
    const int wid  = tid >> 5;
    const int wm   = wid & 3;        // 0..3 (m)
    const int wn   = wid >> 2;       // 0..1 (n group)
    const int lj   = lane >> 3;
    const int lr   = lane & 7;
    const int mblk  = blockIdx.x >> 1;
    const int nhalf = blockIdx.x & 1;
    const int m0    = mblk * 128;
    const int nbase = nhalf * (Nn / 2);

    const uint32_t mbF = sbase + SM_MB;
    const uint32_t mbE = sbase + SM_MB + 32;
    const uint32_t mbA = sbase + SM_MB + 64;

    if (tid == 0) {
#pragma unroll
        for (int i = 0; i < 4; i++) {
            MBAR_INIT(mbF + i * 8, 128);
            MBAR_INIT(mbE + i * 8, 128);
        }
        MBAR_INIT(mbA, 256);
    }
    __syncthreads();

    // ---- prologue: A + own group's B halves for tiles 0,1 ----
    {
        const char* srcA = (const char*)g_qz + (size_t)m0 * 256;
#pragma unroll
        for (int i = 0; i < 8; i++) {
            int f = tid + i * 256;
            int m = f >> 4, c = f & 15;
            cp_async16(sbase + SM_A + ROWSWZ(m, c), srcA + (size_t)m * 256 + c * 16);
        }
        CPASYNC_MBAR_ARRIVE(mbA);

        const int lt = tid & 127;
#pragma unroll
        for (int s = 0; s < 2; s++) {
            const char* srcB = (const char*)g_qw +
                ((size_t)nbase + s * 128 + wn * 64) * 256;
            uint32_t dst = sbase + (s ? SM_B1 : SM_B0) + wn * 16384;
#pragma unroll
            for (int i = 0; i < 8; i++) {
                int f = lt + i * 128;
                int n = f >> 4, c = f & 15;
                cp_async16(dst + ROWSWZ(n, c), srcB + (size_t)n * 256 + c * 16);
            }
            CPASYNC_MBAR_ARRIVE(mbF + (s * 2 + wn) * 8);
        }
    }

    float izv[4];
#pragma unroll
    for (int s = 0; s < 4; s++)
        izv[s] = __ldg(&g_izs[m0 + wm * 32 + (s >> 1) * 16 + (s & 1) * 8 + (lane >> 2)]);

    uint32_t aRow[2], aOff0[2];
#pragma unroll
    for (int mt = 0; mt < 2; mt++) {
        int ml = wm * 32 + mt * 16 + ((lj & 1) << 3) + lr;
        uint32_t cA0 = (uint32_t)(lj >> 1);
        aRow[mt]  = sbase + SM_A + (uint32_t)ml * 256;
        aOff0[mt] = (((cA0 & 8) | ((cA0 ^ (uint32_t)(ml & 7)) & 7)) << 4);
    }
    uint32_t bRel[4], bOff0[4];
#pragma unroll
    for (int p = 0; p < 4; p++) {
        int nl = p * 16 + ((lj >> 1) << 3) + lr;
        uint32_t cB0 = (uint32_t)(lj & 1);
        bRel[p]  = (uint32_t)nl * 256 + (uint32_t)wn * 16384;
        bOff0[p] = (((cB0 & 8) | ((cB0 ^ (uint32_t)(nl & 7)) & 7)) << 4);
    }

    float bv[4][4];
    int   bi[4][4];
#pragma unroll
    for (int s = 0; s < 4; s++)
#pragma unroll
        for (int e = 0; e < 4; e++) { bv[s][e] = -3.4e38f; bi[s][e] = 0; }

#define TOP4_INS(S, VAL, IDX)                                              \
    if ((VAL) > bv[S][3]) {                                                \
        float _cv = (VAL); int _ci = (IDX);                                \
        _Pragma("unroll")                                                  \
        for (int _q = 0; _q < 4; _q++) {                                   \
            if (_cv > bv[S][_q]) {                                         \
                float _tv = bv[S][_q]; int _ti = bi[S][_q];                \
                bv[S][_q] = _cv; bi[S][_q] = _ci; _cv = _tv; _ci = _ti;    \
            }                                                              \
        }                                                                  \
    }

    const int lt = tid & 127;
    bool awaited = false;
    for (int t = 0; t < NTILE; t++) {
        const int s = t & 1;
        const uint32_t par = (uint32_t)((t >> 1) & 1);
        const uint32_t cur = sbase + (s ? SM_B1 : SM_B0);
        const uint32_t mb_full  = mbF + (s * 2 + wn) * 8;
        const uint32_t mb_empty = mbE + (s * 2 + wn) * 8;

        mbar_wait(mb_full, par);
        if (!awaited) { mbar_wait(mbA, 0); awaited = true; }

        int C[2][8][4];
#pragma unroll
        for (int mt = 0; mt < 2; mt++)
#pragma unroll
            for (int f = 0; f < 8; f++)
#pragma unroll
                for (int e = 0; e < 4; e++) C[mt][f][e] = 0;

#pragma unroll
        for (int ks = 0; ks < 8; ks++) {
            const uint32_t kx = (uint32_t)(ks << 5);
            uint32_t a[2][4];
#pragma unroll
            for (int mt = 0; mt < 2; mt++) {
                LDSM_X4(a[mt][0], a[mt][1], a[mt][2], a[mt][3],
                        aRow[mt] + (aOff0[mt] ^ kx));
            }
            uint32_t b[8][2];
#pragma unroll
            for (int p = 0; p < 4; p++) {
                LDSM_X4(b[2 * p][0], b[2 * p][1], b[2 * p + 1][0], b[2 * p + 1][1],
                        cur + bRel[p] + (bOff0[p] ^ kx));
            }
#pragma unroll
            for (int mt = 0; mt < 2; mt++)
#pragma unroll
                for (int f = 0; f < 8; f++)
                    IMMA16832(C[mt][f], a[mt], b[f]);
        }

        MBAR_ARRIVE(mb_empty);

        // epilogue (overlaps the other group's MMA phase)
        const int cbase = nbase + t * 128 + wn * 64 + 2 * (lane & 3);
#pragma unroll
        for (int f = 0; f < 8; f++) {
            float2 wv2 = __ldg((const float2*)(g_wnorm + cbase + f * 8));
            float2 iw2 = __ldg((const float2*)(g_iws  + cbase + f * 8));
#pragma unroll
            for (int e = 0; e < 2; e++) {
                int col = cbase + f * 8 + e;
                float wvv = e ? wv2.y : wv2.x;
                float iww = e ? iw2.y : iw2.x;
#pragma unroll
                for (int mt = 0; mt < 2; mt++) {
                    float s0 = __int2float_rn(C[mt][f][e])     * iww * izv[mt * 2 + 0] - wvv;
                    float s1 = __int2float_rn(C[mt][f][2 + e]) * iww * izv[mt * 2 + 1] - wvv;
                    TOP4_INS(mt * 2 + 0, s0, col);
                    TOP4_INS(mt * 2 + 1, s1, col);
                }
            }
        }

        if (t + 2 < NTILE) {
            mbar_wait(mb_empty, par);
            const char* src = (const char*)g_qw +
                ((size_t)nbase + (t + 2) * 128 + wn * 64) * 256;
#pragma unroll
            for (int i = 0; i < 8; i++) {
                int f = lt + i * 128;
                int n = f >> 4, c = f & 15;
                cp_async16(cur + (uint32_t)wn * 16384 + ROWSWZ(n, c),
                           src + (size_t)n * 256 + c * 16);
            }
            CPASYNC_MBAR_ARRIVE(mb_full);
        }
    }

    __syncthreads();

    // ---- cross-thread merge: 32 candidates/row -> top-16 (values + idx) ----
    float* MV = (float*)(smem + SM_MV);   // [128][32]
    int*   MI = (int*)  (smem + SM_MI);
#pragma unroll
    for (int s = 0; s < 4; s++) {
        int row = wm * 32 + (s >> 1) * 16 + (s & 1) * 8 + (lane >> 2);
        int col = wn * 16 + (lane & 3) * 4;
#pragma unroll
        for (int e = 0; e < 4; e++) {
            MV[row * 32 + col + e] = bv[s][e];
            MI[row * 32 + col + e] = bi[s][e];
        }
    }
    __syncthreads();

    if (tid < 128) {
        int row = tid;
        float tv[NCAND];
        int   ti[NCAND];
#pragma unroll
        for (int e = 0; e < NCAND; e++) { tv[e] = -3.4e38f; ti[e] = 0; }
        for (int k = 0; k < 32; k++) {
            float v  = MV[row * 32 + k];
            int   ix = MI[row * 32 + k];
            if (v > tv[NCAND - 1]) {
                float cv = v; int ci = ix;
#pragma unroll
                for (int q = 0; q < NCAND; q++) {
                    if (cv > tv[q]) {
                        float xv = tv[q]; int xi = ti[q];
                        tv[q] = cv; ti[q] = ci; cv = xv; ci = xi;
                    }
                }
            }
        }
        int m = m0 + row;
#pragma unroll
        for (int e = 0; e < NCAND; e++) {
            g_cand[m][nhalf][e]  = ti[e];
            g_candv[m][nhalf][e] = tv[e];
        }
        if (tv[0] - tv[NCAND - 1] <= CERT_WINDOW) {
            atomicOr(&g_flag[m], 1);
            int p = atomicAdd(&g_flag_count, 1);
            g_flag_list[p] = m;
        }
    }
}

// ---------------------------------------------------------------------------
// 4) Value-pruned exact rescore + fused z_q gather (one warp per row).
//    Only candidates with approx v >= v0_global - CERT_WINDOW can win.
// ---------------------------------------------------------------------------
__global__ __launch_bounds__(256) void rescore_kernel(const float* __restrict__ zout,
                                                      const float* __restrict__ w,
                                                      float* __restrict__ idxf,
                                                      float* __restrict__ zq) {
    int m    = (blockIdx.x * blockDim.x + threadIdx.x) >> 5;
    int lane = threadIdx.x & 31;
    if (m >= Mn) return;
    if (g_flag[m]) return;

    float zr[8];
    const float* zp = zout + (size_t)m * Kn;
#pragma unroll
    for (int j = 0; j < 8; j++) zr[j] = zp[lane + 32 * j];

    const int*   cp = g_cand[m][0];    // 32 contiguous entries
    const float* vp = g_candv[m][0];
    float v0g = fmaxf(vp[0], vp[NCAND]);   // global approx max = max of half-maxima
    float thr = v0g - CERT_WINDOW;

    float bestS = -3.4e38f;
    int   bestI = 0x7fffffff;
    for (int c = 0; c < 2 * NCAND; c++) {
        if (vp[c] < thr) continue;         // cannot win (|exact-approx| <= e)
        int idx = cp[c];
        const float* wp = w + (size_t)idx * Kn;
        float s = 0.f;
#pragma unroll
        for (int j = 0; j < 8; j++) s += zr[j] * wp[lane + 32 * j];
#pragma unroll
        for (int o = 16; o > 0; o >>= 1) s += __shfl_xor_sync(0xffffffffu, s, o);
        s -= g_wnorm[idx];
        if (s > bestS || (s == bestS && idx < bestI)) { bestS = s; bestI = idx; }
    }
    if (lane == 0) {
        g_bestidx[m] = bestI;
        idxf[m] = (float)bestI;
    }
    const float4* src = (const float4*)(w + (size_t)bestI * Kn);
    float4* dst = (float4*)(zq + (size_t)m * Kn);
    dst[lane]      = src[lane];
    dst[lane + 32] = src[lane + 32];
}

// ---------------------------------------------------------------------------
// 5) Fallback full exact scan for flagged rows (+ fused z_q gather)
// ---------------------------------------------------------------------------
__global__ __launch_bounds__(256) void fallback_kernel(const float* __restrict__ zout,
                                                       const float* __restrict__ w,
                                                       float* __restrict__ idxf,
                                                       float* __restrict__ zq) {
    __shared__ float sv[8];
    __shared__ int   si[8];
    __shared__ int   sbest;
    int nflag = g_flag_count;
    int wi = threadIdx.x >> 5, lane = threadIdx.x & 31;
    for (int r = blockIdx.x; r < nflag; r += gridDim.x) {
        int m = g_flag_list[r];
        float zr[8];
        const float* zp = zout + (size_t)m * Kn;
#pragma unroll
        for (int j = 0; j < 8; j++) zr[j] = zp[lane + 32 * j];
        float bS = -3.4e38f;
        int   bI = 0x7fffffff;
        for (int n = wi; n < Nn; n += 8) {
            const float* wp = w + (size_t)n * Kn;
            float s = 0.f;
#pragma unroll
            for (int j = 0; j < 8; j++) s += zr[j] * wp[lane + 32 * j];
#pragma unroll
            for (int o = 16; o > 0; o >>= 1) s += __shfl_xor_sync(0xffffffffu, s, o);
            s -= g_wnorm[n];
            if (s > bS || (s == bS && n < bI)) { bS = s; bI = n; }
        }
        if (lane == 0) { sv[wi] = bS; si[wi] = bI; }
        __syncthreads();
        if (threadIdx.x == 0) {
            float bvv = sv[0]; int bii = si[0];
#pragma unroll
            for (int q = 1; q < 8; q++) {
                if (sv[q] > bvv || (sv[q] == bvv && si[q] < bii)) { bvv = sv[q]; bii = si[q]; }
            }
            g_bestidx[m] = bii;
            idxf[m] = (float)bii;
            sbest = bii;
        }
        __syncthreads();
        int bii = sbest;
        if (threadIdx.x < 64) {
            ((float4*)(zq + (size_t)m * Kn))[threadIdx.x] =
                ((const float4*)(w + (size_t)bii * Kn))[threadIdx.x];
        }
        __syncthreads();
    }
}

// ---------------------------------------------------------------------------
extern "C" void kernel_launch(void* const* d_in, const int* in_sizes, int n_in,
                              void* d_out, int out_size) {
    const float* z = (const float*)d_in[0];
    const float* w = (const float*)d_in[1];
    float* out   = (float*)d_out;
    float* z_out = out;
    float* z_q   = out + OUT_ZQ;
    float* idxf  = out + OUT_IDX;

    cudaFuncSetAttribute(gemm_kernel,
                         cudaFuncAttributeMaxDynamicSharedMemorySize, SMEM_BYTES);

    dim3 tt(32, 8);
    transpose_kernel<<<dim3(HWn / 32, Kn / 32, Bln), tt>>>(z, z_out);
    zwquant_kernel<<<Mn / 8 + Nn / 8, 256>>>(z_out, w);
    gemm_kernel<<<(Mn / 128) * 2, 256, SMEM_BYTES>>>();
    rescore_kernel<<<Mn / 8, 256>>>(z_out, w, idxf, z_q);
    fallback_kernel<<<128, 256>>>(z_out, w, idxf, z_q);
}